// round 7
// baseline (speedup 1.0000x reference)
#include <cuda_runtime.h>
#include <math.h>
#include <stdint.h>

#define HID    2560
#define BATCH  64
#define TSTEPS 500
#define IN_DIM 128
#define GRID   80
#define ROFF2   17408                       // W area: 64 rows * 272B
#define STAGE   26112                       // + r area: 32 rows * 272B
#define MRG_OFF (4*STAGE)                   // 104448
#define MRG_STR 4352                        // 64*17*4
#define SMEM_TOTAL (MRG_OFF + 8*MRG_STR)    // 139264

// static scratch (allocations forbidden)
__device__ __align__(16) float g_Wb2[900*4096];            // [slab64][64h][64k] permuted tf32 W_eff
__device__ __align__(16) float g_intf[TSTEPS*BATCH*IN_DIM];// tf32 inputs, k-permuted
__device__ __align__(16) float g_r[2][BATCH*HID];          // tf32 rates ping-pong [b][h-permuted]
__device__ int g_bar;

// column-pair permutation within aligned 16-groups:
// storage pos p holds logical col lmap(p); logical l stored at pmap(l)
__host__ __device__ __forceinline__ int lmap(int p) {
    return (p & 8) + ((p & 7) >> 1) + ((p & 1) << 2);
}
__host__ __device__ __forceinline__ int pmap(int l) {
    return (l & 8) + ((l & 3) << 1) + ((l >> 2) & 1);
}

// ---------------------------------------------------------------------------
// Builders. Connectivity (validated at rel_err 1e-8 in fp32 rounds):
//  E col k(<2048): |area(h)-area(k)|<=1, +|w|; I col: same area, -|w|;
//  diagonal removed; input cols only for area-0 rows, +|w_in|.
// 64k slabs per 64h tile: nE64 E-slabs, 2 I-slabs, (area0) 2 input slabs.
// area slab bases {0,200,460,720}; nE64 {16,24,24,16}; nS {20,26,26,18}.
// ---------------------------------------------------------------------------
__global__ void build_W(const float* __restrict__ W_rec, const float* __restrict__ W_in) {
    int idx = blockIdx.x*blockDim.x + threadIdx.x;
    if (idx >= 900*4096) return;
    int blk = idx >> 12, e = idx & 4095;
    int hl = e >> 6, cc = e & 63;
    int c_log = (cc & ~15) + lmap(cc & 15);
    int a    = (blk<200)?0:(blk<460)?1:(blk<720)?2:3;
    int base = (a==0)?0:(a==1)?200:(a==2)?460:720;
    int nE64 = (a==1||a==2)?24:16;
    int nS   = nE64 + 2 + ((a==0)?2:0);
    int ti = (blk - base)/nS;
    int i  = (blk - base) - ti*nS;
    int hbase = (ti<8) ? a*512 + ti*64 : 2048 + a*128 + (ti-8)*64;
    int h = hbase + hl;
    float v = 0.f;
    if (i < nE64) {
        int k = (a>0?a-1:0)*512 + i*64 + c_log;
        if (k != h) v = fabsf(W_rec[(size_t)h*HID + k]);
    } else if (i < nE64+2) {
        int k = 2048 + a*128 + (i-nE64)*64 + c_log;
        if (k != h) v = -fabsf(W_rec[(size_t)h*HID + k]);
    } else {
        int kin = (i-nE64-2)*64 + c_log;
        v = fabsf(W_in[(size_t)h*IN_DIM + kin]);
    }
    uint32_t o; asm("cvt.rna.tf32.f32 %0, %1;" : "=r"(o) : "f"(v));
    g_Wb2[idx] = __uint_as_float(o);
}

__global__ void build_in(const float* __restrict__ in) {
    int idx = blockIdx.x*blockDim.x + threadIdx.x;
    if (idx >= TSTEPS*BATCH*IN_DIM) return;
    int ks = idx & 127;
    int k_log = (ks & ~15) + lmap(ks & 15);
    uint32_t o; asm("cvt.rna.tf32.f32 %0, %1;" : "=r"(o) : "f"(in[(idx & ~127) + k_log]));
    g_intf[idx] = __uint_as_float(o);
}

__global__ void init_k() {
    int idx = blockIdx.x*blockDim.x + threadIdx.x;
    if (idx < BATCH*HID) g_r[0][idx] = 0.f;   // r0 = retanh(0) = 0
    if (idx == 0) g_bar = 0;
}

// ---------------------------------------------------------------------------
__device__ __forceinline__ void cp16(uint32_t d, const void* s) {
    asm volatile("cp.async.cg.shared.global [%0], [%1], 16;" :: "r"(d), "l"(s) : "memory");
}
__device__ __forceinline__ void cpcommit() { asm volatile("cp.async.commit_group;" ::: "memory"); }
__device__ __forceinline__ void cpwait(int n) {
    if (n >= 2)      asm volatile("cp.async.wait_group 2;" ::: "memory");
    else if (n == 1) asm volatile("cp.async.wait_group 1;" ::: "memory");
    else             asm volatile("cp.async.wait_group 0;" ::: "memory");
}

// ---------------------------------------------------------------------------
// Persistent kernel: 80 CTAs (40 h-tiles x 2 batch halves) x 256 threads.
// Warp wid = nh*4 + kq: nh picks 16-batch half of the 32b tile, kq a 16-k slice.
// ---------------------------------------------------------------------------
__global__ void __launch_bounds__(256, 1) rnn_kernel(const float* __restrict__ b_rec,
                                                     float* __restrict__ out) {
    extern __shared__ char sm[];
    uint32_t sb;
    asm("{ .reg .u64 t; cvta.to.shared.u64 t, %1; cvt.u32.u64 %0, t; }" : "=r"(sb) : "l"(sm));
    const int tid = threadIdx.x, wid = tid >> 5, lane = tid & 31;
    const int g = lane >> 2, cq = lane & 3;
    const int kq = wid & 3, nh = wid >> 2;
    const int cta = blockIdx.x, tau = cta >> 1, bh = (cta & 1) << 5;
    const int a = tau/10, ti = tau - 10*a;
    const int hbase = (ti<8) ? a*512 + ti*64 : 2048 + a*128 + (ti-8)*64;
    const int nE64  = (a==1||a==2)?24:16;
    const int nS    = nE64 + 2 + ((a==0)?2:0);
    const int kE0   = (a>0?a-1:0)*512;
    const int kI0   = 2048 + a*128;
    const int baseA = (a==0)?0:(a==1)?200:(a==2)?460:720;
    const int blkbase = baseA + ti*nS;
    const float bias = b_rec[hbase + (tid & 63)];
    const int kwofs = (kq*16 + 2*cq) * 4;       // byte offset of this lane's col-pair

    float x[8];
    #pragma unroll
    for (int i = 0; i < 8; i++) x[i] = 0.f;

    for (int t = 0; t < TSTEPS; t++) {
        const float* __restrict__ rin  = g_r[t & 1];
        float*       __restrict__ rout = g_r[(t & 1) ^ 1];
        const float* __restrict__ inp  = g_intf + (size_t)t * (BATCH*IN_DIM);

        auto issue_slab = [&](int s) {
            uint32_t st = sb + (uint32_t)(s & 3)*STAGE;
            const float* wsrc = g_Wb2 + (size_t)(blkbase + s)*4096;
            #pragma unroll
            for (int it = 0; it < 4; it++) {
                int c = tid + 256*it;                  // 1024 chunks of 16B
                cp16(st + (uint32_t)(c>>4)*272 + (c&15)*16, wsrc + c*4);
            }
            const float* rsrc; int rstr, k0;
            if (s < nE64)        { rsrc = rin; rstr = HID;    k0 = kE0 + 64*s; }
            else if (s < nE64+2) { rsrc = rin; rstr = HID;    k0 = kI0 + 64*(s-nE64); }
            else                 { rsrc = inp; rstr = IN_DIM; k0 = 64*(s-nE64-2); }
            #pragma unroll
            for (int it = 0; it < 2; it++) {
                int c = tid + 256*it;                  // 512 chunks
                cp16(st + ROFF2 + (uint32_t)(c>>4)*272 + (c&15)*16,
                     rsrc + (size_t)(bh + (c>>4))*rstr + k0 + (c&15)*4);
            }
            cpcommit();
        };

        issue_slab(0); issue_slab(1); issue_slab(2);

        float acc[4][2][4];
        #pragma unroll
        for (int i = 0; i < 4; i++)
            #pragma unroll
            for (int j = 0; j < 2; j++)
                #pragma unroll
                for (int k = 0; k < 4; k++) acc[i][j][k] = 0.f;

        for (int s = 0; s < nS; s++) {
            int ahead = nS - 1 - s; if (ahead > 2) ahead = 2;
            cpwait(ahead);
            __syncthreads();
            if (s + 3 < nS) issue_slab(s + 3);

            const char* st = sm + (size_t)(s & 3)*STAGE;
            float2 aL[4][2], aH[4][2], bb[2][2];
            #pragma unroll
            for (int i = 0; i < 4; i++) {
                const char* r0 = st + (16*i + g)*272 + kwofs;
                const char* r8 = st + (16*i + g + 8)*272 + kwofs;
                aL[i][0] = *(const float2*)(r0);
                aH[i][0] = *(const float2*)(r8);
                aL[i][1] = *(const float2*)(r0 + 32);
                aH[i][1] = *(const float2*)(r8 + 32);
            }
            #pragma unroll
            for (int j = 0; j < 2; j++) {
                const char* rp = st + ROFF2 + (nh*16 + 8*j + g)*272 + kwofs;
                bb[j][0] = *(const float2*)(rp);
                bb[j][1] = *(const float2*)(rp + 32);
            }
            #pragma unroll
            for (int grp = 0; grp < 2; grp++)
                #pragma unroll
                for (int i = 0; i < 4; i++)
                    #pragma unroll
                    for (int j = 0; j < 2; j++)
                        asm volatile(
                            "mma.sync.aligned.m16n8k8.row.col.f32.tf32.tf32.f32 "
                            "{%0,%1,%2,%3},{%4,%5,%6,%7},{%8,%9},{%0,%1,%2,%3};"
                            : "+f"(acc[i][j][0]), "+f"(acc[i][j][1]),
                              "+f"(acc[i][j][2]), "+f"(acc[i][j][3])
                            : "r"(__float_as_uint(aL[i][grp].x)),
                              "r"(__float_as_uint(aH[i][grp].x)),
                              "r"(__float_as_uint(aL[i][grp].y)),
                              "r"(__float_as_uint(aH[i][grp].y)),
                              "r"(__float_as_uint(bb[j][grp].x)),
                              "r"(__float_as_uint(bb[j][grp].y)));
        }

        // merge 4 k-split partials via smem (per-warp region, stride-17 rows)
        {
            char* mb = sm + MRG_OFF + wid*MRG_STR;
            #pragma unroll
            for (int i = 0; i < 4; i++)
                #pragma unroll
                for (int j = 0; j < 2; j++) {
                    int c = 8*j + 2*cq;
                    *(float*)(mb + (((16*i+g  )*17 + c  ))*4) = acc[i][j][0];
                    *(float*)(mb + (((16*i+g  )*17 + c+1))*4) = acc[i][j][1];
                    *(float*)(mb + (((16*i+g+8)*17 + c  ))*4) = acc[i][j][2];
                    *(float*)(mb + (((16*i+g+8)*17 + c+1))*4) = acc[i][j][3];
                }
        }
        __syncthreads();

        // epilogue: thread owns h = tid&63, 8 batches bl = (tid>>6)*8 + ii
        const int hh = tid & 63;
        const int bq = tid >> 6;
        const int hst = (hh & ~15) + pmap(hh & 15);
        #pragma unroll
        for (int ii = 0; ii < 8; ii++) {
            int bl = bq*8 + ii;
            int nh2 = bl >> 4, col = bl & 15;
            const char* mrow = sm + MRG_OFF + (size_t)(nh2*4)*MRG_STR + ((hh*17 + col) << 2);
            float sum = *(const float*)(mrow)
                      + *(const float*)(mrow +   MRG_STR)
                      + *(const float*)(mrow + 2*MRG_STR)
                      + *(const float*)(mrow + 3*MRG_STR);
            float pre = sum + bias;
            float xv  = 0.8f*x[ii] + 0.2f*pre;
            x[ii] = xv;
            float r = (xv > 0.f) ? tanhf(xv) : 0.f;
            out[(size_t)t*(BATCH*HID) + (size_t)(bh + bl)*HID + hbase + hh] = r;
            uint32_t o; asm("cvt.rna.tf32.f32 %0, %1;" : "=r"(o) : "f"(r));
            rout[(size_t)(bh + bl)*HID + hbase + hst] = __uint_as_float(o);
        }

        // grid barrier (monotonic counter; 80 CTAs co-resident)
        __threadfence();
        __syncthreads();
        if (tid == 0) {
            atomicAdd(&g_bar, 1);
            while (*((volatile int*)&g_bar) < GRID*(t+1)) { }
        }
        __syncthreads();
        __threadfence();
    }
}

// ---------------------------------------------------------------------------
extern "C" void kernel_launch(void* const* d_in, const int* in_sizes, int n_in,
                              void* d_out, int out_size) {
    const float *inputs = nullptr, *W_rec = nullptr,
                *b_rec = nullptr,  *W_in  = nullptr;
    for (int i = 0; i < n_in; i++) {
        long n = (long)in_sizes[i];
        if      (n == (long)TSTEPS*BATCH*IN_DIM) inputs = (const float*)d_in[i];
        else if (n == (long)HID*HID)             W_rec  = (const float*)d_in[i];
        else if (n == (long)HID)                 b_rec  = (const float*)d_in[i];
        else if (n == (long)HID*IN_DIM)          W_in   = (const float*)d_in[i];
    }
    float* out = (float*)d_out;

    cudaFuncSetAttribute(rnn_kernel, cudaFuncAttributeMaxDynamicSharedMemorySize, SMEM_TOTAL);

    build_W <<<(900*4096 + 255)/256, 256>>>(W_rec, W_in);
    build_in<<<(TSTEPS*BATCH*IN_DIM + 255)/256, 256>>>(inputs);
    init_k  <<<(BATCH*HID + 255)/256, 256>>>();
    rnn_kernel<<<GRID, 256, SMEM_TOTAL>>>(b_rec, out);
}

// round 8
// speedup vs baseline: 2.1070x; 2.1070x over previous
#include <cuda_runtime.h>
#include <cuda_bf16.h>
#include <math.h>
#include <stdint.h>

#define HID    2560
#define BATCH  64
#define TSTEPS 500
#define IN_DIM 128
#define GRID   80
#define STAGE_SZ 12288                 // 8KB W (64x128B) + 4KB r (32x128B)
#define NSTG   5
#define OUT_OFF (NSTG*STAGE_SZ)        // 61440
#define SMEM_TOTAL (OUT_OFF + 32*68*4) // 70144

// static scratch (allocations forbidden)
__device__ __nv_bfloat16 g_Wb[900*4096];              // blocked bf16 W_eff [slab][64h][64k]
__device__ __nv_bfloat16 g_in[TSTEPS*BATCH*IN_DIM];   // bf16 inputs
__device__ __nv_bfloat16 g_r[2][BATCH*HID];           // bf16 rates ping-pong [b][h]
__device__ int g_bar;

// ---------------------------------------------------------------------------
// Builders. Connectivity (validated at rel_err 1e-8 in fp32 rounds):
//  E col k(<2048): |area(h)-area(k)|<=1, +|w|; I col: same area, -|w|;
//  diagonal removed; input cols only for area-0 rows, +|w_in|.
// 64k slabs per 64h tile: nE64 {16,24,24,16}, +2 I, (+2 input if area 0)
// → nS {20,26,26,18}; slab bases per area {0,200,460,720}; total 900.
// ---------------------------------------------------------------------------
__global__ void build_W(const float* __restrict__ W_rec, const float* __restrict__ W_in) {
    int idx = blockIdx.x*blockDim.x + threadIdx.x;
    if (idx >= 900*4096) return;
    int blk = idx >> 12, e = idx & 4095;
    int hl = e >> 6, cc = e & 63;
    int a    = (blk<200)?0:(blk<460)?1:(blk<720)?2:3;
    int base = (a==0)?0:(a==1)?200:(a==2)?460:720;
    int nE64 = (a==1||a==2)?24:16;
    int nS   = nE64 + 2 + ((a==0)?2:0);
    int ti = (blk - base)/nS;
    int i  = (blk - base) - ti*nS;
    int hbase = (ti<8) ? a*512 + ti*64 : 2048 + a*128 + (ti-8)*64;
    int h = hbase + hl;
    float v = 0.f;
    if (i < nE64) {
        int k = (a>0?a-1:0)*512 + i*64 + cc;
        if (k != h) v = fabsf(W_rec[(size_t)h*HID + k]);
    } else if (i < nE64+2) {
        int k = 2048 + a*128 + (i-nE64)*64 + cc;
        if (k != h) v = -fabsf(W_rec[(size_t)h*HID + k]);
    } else {
        int kin = (i-nE64-2)*64 + cc;
        v = fabsf(W_in[(size_t)h*IN_DIM + kin]);
    }
    g_Wb[idx] = __float2bfloat16_rn(v);
}

__global__ void build_in(const float* __restrict__ in) {
    int idx = blockIdx.x*blockDim.x + threadIdx.x;
    if (idx >= TSTEPS*BATCH*IN_DIM) return;
    g_in[idx] = __float2bfloat16_rn(in[idx]);
}

__global__ void init_k() {
    int idx = blockIdx.x*blockDim.x + threadIdx.x;
    if (idx < BATCH*HID) g_r[0][idx] = __float2bfloat16_rn(0.f);
    if (idx == 0) g_bar = 0;
}

// ---------------------------------------------------------------------------
__device__ __forceinline__ void cp16(uint32_t d, const void* s) {
    asm volatile("cp.async.cg.shared.global [%0], [%1], 16;" :: "r"(d), "l"(s) : "memory");
}
__device__ __forceinline__ void cpcommit() { asm volatile("cp.async.commit_group;" ::: "memory"); }
__device__ __forceinline__ void cpwait(int n) {
    if (n >= 3)      asm volatile("cp.async.wait_group 3;" ::: "memory");
    else if (n == 2) asm volatile("cp.async.wait_group 2;" ::: "memory");
    else if (n == 1) asm volatile("cp.async.wait_group 1;" ::: "memory");
    else             asm volatile("cp.async.wait_group 0;" ::: "memory");
}
#define LDSM_X4(r0,r1,r2,r3,addr) \
    asm volatile("ldmatrix.sync.aligned.m8n8.x4.shared.b16 {%0,%1,%2,%3}, [%4];" \
        : "=r"(r0),"=r"(r1),"=r"(r2),"=r"(r3) : "r"(addr))
#define MMA_BF16(c, a0,a1,a2,a3, b0,b1) \
    asm volatile("mma.sync.aligned.m16n8k16.row.col.f32.bf16.bf16.f32 " \
        "{%0,%1,%2,%3},{%4,%5,%6,%7},{%8,%9},{%0,%1,%2,%3};" \
        : "+f"((c)[0]),"+f"((c)[1]),"+f"((c)[2]),"+f"((c)[3]) \
        : "r"(a0),"r"(a1),"r"(a2),"r"(a3),"r"(b0),"r"(b1))

// ---------------------------------------------------------------------------
// Persistent kernel: 80 CTAs (40 h-tiles x 2 batch halves) x 256 threads.
// 8 warps = 4m x 2n (warp tile m16 x n16), no k-split, x in fragment regs.
// ---------------------------------------------------------------------------
__global__ void __launch_bounds__(256, 1) rnn_kernel(const float* __restrict__ b_rec,
                                                     float* __restrict__ out) {
    extern __shared__ char sm[];
    uint32_t sb;
    asm("{ .reg .u64 t; cvta.to.shared.u64 t, %1; cvt.u32.u64 %0, t; }" : "=r"(sb) : "l"(sm));
    const int tid = threadIdx.x, wid = tid >> 5, lane = tid & 31;
    const int wm = wid & 3, nh = wid >> 2;
    const int g = lane >> 2, cq = lane & 3;
    const int cta = blockIdx.x, tau = cta >> 1, bh = (cta & 1) << 5;
    const int a = tau/10, ti = tau - 10*a;
    const int hbase = (ti<8) ? a*512 + ti*64 : 2048 + a*128 + (ti-8)*64;
    const int nE64  = (a==1||a==2)?24:16;
    const int nS    = nE64 + 2 + ((a==0)?2:0);
    const int kE0   = (a>0?a-1:0)*512;
    const int kI0   = 2048 + a*128;
    const int baseA = (a==0)?0:(a==1)?200:(a==2)?460:720;
    const int blkbase = baseA + ti*nS;

    const float bias0 = b_rec[hbase + wm*16 + g];
    const float bias1 = b_rec[hbase + wm*16 + 8 + g];

    // ldmatrix lane geometry (chunk-XOR swizzle: chunk' = chunk ^ (row&7))
    const int lr = lane & 7, half = (lane >> 3) & 1, kbit = lane >> 4;
    const int rowA = wm*16 + half*8 + lr;
    const int rowB = nh*16 + half*8 + lr;
    const uint32_t aoff = (uint32_t)rowA * 128;
    const uint32_t boff = 8192u + (uint32_t)rowB * 128;
    const int axor = rowA & 7, bxor = rowB & 7;

    float x0[4], x1[4];
    #pragma unroll
    for (int k = 0; k < 4; k++) { x0[k] = 0.f; x1[k] = 0.f; }

    float* OUT = (float*)(sm + OUT_OFF);   // [32b][68] padded fp32

    for (int t = 0; t < TSTEPS; t++) {
        const __nv_bfloat16* __restrict__ rin  = g_r[t & 1];
        __nv_bfloat16*       __restrict__ rout = g_r[(t & 1) ^ 1];
        const __nv_bfloat16* __restrict__ inp  = g_in + (size_t)t * (BATCH*IN_DIM);

        auto issue_slab = [&](int s) {
            uint32_t st = sb + (uint32_t)(s % NSTG) * STAGE_SZ;
            const __nv_bfloat16* wsrc = g_Wb + (size_t)(blkbase + s) * 4096;
            #pragma unroll
            for (int it = 0; it < 2; it++) {
                int c = tid + 256*it;              // 512 W chunks of 16B
                int row = c >> 3, ch = c & 7;
                cp16(st + ((uint32_t)row << 7) + (uint32_t)((ch ^ (row & 7)) << 4),
                     wsrc + c*8);
            }
            {
                int c = tid;                        // 256 r chunks
                int row = c >> 3, ch = c & 7;
                const __nv_bfloat16* src;
                if (s < nE64)        src = rin + (size_t)(bh + row)*HID    + kE0 + 64*s + ch*8;
                else if (s < nE64+2) src = rin + (size_t)(bh + row)*HID    + kI0 + 64*(s-nE64) + ch*8;
                else                 src = inp + (size_t)(bh + row)*IN_DIM + 64*(s-nE64-2) + ch*8;
                cp16(st + 8192u + ((uint32_t)row << 7) + (uint32_t)((ch ^ (row & 7)) << 4),
                     src);
            }
            cpcommit();
        };

        issue_slab(0); issue_slab(1); issue_slab(2); issue_slab(3);

        float acc0[4], acc1[4];
        #pragma unroll
        for (int k = 0; k < 4; k++) { acc0[k] = 0.f; acc1[k] = 0.f; }

        for (int s = 0; s < nS; s++) {
            int ahead = nS - 1 - s; if (ahead > 3) ahead = 3;
            cpwait(ahead);
            __syncthreads();
            if (s + 4 < nS) issue_slab(s + 4);

            uint32_t st = sb + (uint32_t)(s % NSTG) * STAGE_SZ;
            uint32_t pa = st + aoff, pb = st + boff;
            #pragma unroll
            for (int c = 0; c < 4; c++) {
                uint32_t ra0, ra1, ra2, ra3, rb0, rb1, rb2, rb3;
                LDSM_X4(ra0, ra1, ra2, ra3, pa + (uint32_t)(((2*c + kbit) ^ axor) << 4));
                LDSM_X4(rb0, rb1, rb2, rb3, pb + (uint32_t)(((2*c + kbit) ^ bxor) << 4));
                MMA_BF16(acc0, ra0, ra1, ra2, ra3, rb0, rb2);
                MMA_BF16(acc1, ra0, ra1, ra2, ra3, rb1, rb3);
            }
        }

        // epilogue: x update + retanh, transpose via smem, coalesced writes
        {
            int hg = wm*16 + g;
            #pragma unroll
            for (int j = 0; j < 2; j++) {
                float* ac = j ? acc1 : acc0;
                float* xx = j ? x1 : x0;
                int b0 = nh*16 + j*8 + 2*cq;
                float xv, r;
                xv = 0.8f*xx[0] + 0.2f*(ac[0] + bias0); xx[0] = xv;
                r = (xv > 0.f) ? tanhf(xv) : 0.f; OUT[(b0  )*68 + hg    ] = r;
                xv = 0.8f*xx[1] + 0.2f*(ac[1] + bias0); xx[1] = xv;
                r = (xv > 0.f) ? tanhf(xv) : 0.f; OUT[(b0+1)*68 + hg    ] = r;
                xv = 0.8f*xx[2] + 0.2f*(ac[2] + bias1); xx[2] = xv;
                r = (xv > 0.f) ? tanhf(xv) : 0.f; OUT[(b0  )*68 + hg + 8] = r;
                xv = 0.8f*xx[3] + 0.2f*(ac[3] + bias1); xx[3] = xv;
                r = (xv > 0.f) ? tanhf(xv) : 0.f; OUT[(b0+1)*68 + hg + 8] = r;
            }
        }
        __syncthreads();
        #pragma unroll
        for (int it = 0; it < 2; it++) {
            int f = tid + 256*it;                 // 512 float4s: 32b x 16 h-quads
            int b = f >> 4, hq = f & 15;
            float4 v = *(const float4*)&OUT[b*68 + hq*4];
            *(float4*)&out[(size_t)t*(BATCH*HID) + (size_t)(bh + b)*HID + hbase + hq*4] = v;
            uint32_t p0, p1;
            asm("cvt.rn.bf16x2.f32 %0, %1, %2;" : "=r"(p0) : "f"(v.y), "f"(v.x));
            asm("cvt.rn.bf16x2.f32 %0, %1, %2;" : "=r"(p1) : "f"(v.w), "f"(v.z));
            uint2 pk; pk.x = p0; pk.y = p1;
            *(uint2*)(rout + (size_t)(bh + b)*HID + hbase + hq*4) = pk;
        }

        // grid barrier (monotonic counter; 80 CTAs co-resident)
        __threadfence();
        __syncthreads();
        if (tid == 0) {
            atomicAdd(&g_bar, 1);
            while (*((volatile int*)&g_bar) < GRID*(t+1)) { }
        }
        __syncthreads();
    }
}

// ---------------------------------------------------------------------------
extern "C" void kernel_launch(void* const* d_in, const int* in_sizes, int n_in,
                              void* d_out, int out_size) {
    const float *inputs = nullptr, *W_rec = nullptr,
                *b_rec = nullptr,  *W_in  = nullptr;
    for (int i = 0; i < n_in; i++) {
        long n = (long)in_sizes[i];
        if      (n == (long)TSTEPS*BATCH*IN_DIM) inputs = (const float*)d_in[i];
        else if (n == (long)HID*HID)             W_rec  = (const float*)d_in[i];
        else if (n == (long)HID)                 b_rec  = (const float*)d_in[i];
        else if (n == (long)HID*IN_DIM)          W_in   = (const float*)d_in[i];
    }
    float* out = (float*)d_out;

    cudaFuncSetAttribute(rnn_kernel, cudaFuncAttributeMaxDynamicSharedMemorySize, SMEM_TOTAL);

    build_W <<<(900*4096 + 255)/256, 256>>>(W_rec, W_in);
    build_in<<<(TSTEPS*BATCH*IN_DIM + 255)/256, 256>>>(inputs);
    init_k  <<<(BATCH*HID + 255)/256, 256>>>();
    rnn_kernel<<<GRID, 256, SMEM_TOTAL>>>(b_rec, out);
}

// round 9
// speedup vs baseline: 2.4648x; 1.1698x over previous
#include <cuda_runtime.h>
#include <cuda_bf16.h>
#include <math.h>
#include <stdint.h>

#define HID    2560
#define BATCH  64
#define TSTEPS 500
#define IN_DIM 128
#define GRID   80
#define NSTG   5
#define STAGE_SZ 24576                 // 16KB W (64x256B) + 8KB r (32x256B)
#define OUT_OFF (NSTG*STAGE_SZ)        // 122880
#define SMEM_TOTAL (OUT_OFF + 32*68*4) // 131584

// static scratch (allocations forbidden)
__device__ __nv_bfloat16 g_Wb[450*8192];              // bf16 W_eff [slab128][64h][128k]
__device__ __nv_bfloat16 g_in[TSTEPS*BATCH*IN_DIM];   // bf16 inputs
__device__ __nv_bfloat16 g_r[2][BATCH*HID];           // bf16 rates ping-pong [b][h]
__device__ int g_bar;

// ---------------------------------------------------------------------------
// Builders. Connectivity (validated at rel_err 1e-8 in fp32 rounds):
//  E col k(<2048): |area(h)-area(k)|<=1, +|w|; I col: same area, -|w|;
//  diagonal removed; input cols only for area-0 rows, +|w_in|.
// 128k slabs per 64h tile: nE128 {8,12,12,8}, +1 I, (+1 input if area 0)
// → nS {10,13,13,9}; slab bases per area {0,100,230,360}; total 450.
// ---------------------------------------------------------------------------
__global__ void build_W(const float* __restrict__ W_rec, const float* __restrict__ W_in) {
    int idx = blockIdx.x*blockDim.x + threadIdx.x;
    if (idx >= 450*8192) return;
    int blk = idx >> 13, e = idx & 8191;
    int hl = e >> 7, cc = e & 127;
    int a    = (blk<100)?0:(blk<230)?1:(blk<360)?2:3;
    int base = (a==0)?0:(a==1)?100:(a==2)?230:360;
    int nE   = (a==1||a==2)?12:8;
    int nS   = nE + 1 + ((a==0)?1:0);
    int ti = (blk - base)/nS;
    int i  = (blk - base) - ti*nS;
    int hbase = (ti<8) ? a*512 + ti*64 : 2048 + a*128 + (ti-8)*64;
    int h = hbase + hl;
    float v = 0.f;
    if (i < nE) {
        int k = (a>0?a-1:0)*512 + i*128 + cc;
        if (k != h) v = fabsf(W_rec[(size_t)h*HID + k]);
    } else if (i == nE) {
        int k = 2048 + a*128 + cc;
        if (k != h) v = -fabsf(W_rec[(size_t)h*HID + k]);
    } else {
        v = fabsf(W_in[(size_t)h*IN_DIM + cc]);
    }
    g_Wb[idx] = __float2bfloat16_rn(v);
}

__global__ void build_in(const float* __restrict__ in) {
    int idx = blockIdx.x*blockDim.x + threadIdx.x;
    if (idx >= TSTEPS*BATCH*IN_DIM) return;
    g_in[idx] = __float2bfloat16_rn(in[idx]);
}

__global__ void init_k() {
    int idx = blockIdx.x*blockDim.x + threadIdx.x;
    if (idx < BATCH*HID) g_r[0][idx] = __float2bfloat16_rn(0.f);
    if (idx == 0) g_bar = 0;
}

// ---------------------------------------------------------------------------
__device__ __forceinline__ void cp16(uint32_t d, const void* s) {
    asm volatile("cp.async.cg.shared.global [%0], [%1], 16;" :: "r"(d), "l"(s) : "memory");
}
__device__ __forceinline__ void cpcommit() { asm volatile("cp.async.commit_group;" ::: "memory"); }
__device__ __forceinline__ void cpwait(int n) {
    if (n >= 3)      asm volatile("cp.async.wait_group 3;" ::: "memory");
    else if (n == 2) asm volatile("cp.async.wait_group 2;" ::: "memory");
    else if (n == 1) asm volatile("cp.async.wait_group 1;" ::: "memory");
    else             asm volatile("cp.async.wait_group 0;" ::: "memory");
}
#define LDSM_X4(r0,r1,r2,r3,addr) \
    asm volatile("ldmatrix.sync.aligned.m8n8.x4.shared.b16 {%0,%1,%2,%3}, [%4];" \
        : "=r"(r0),"=r"(r1),"=r"(r2),"=r"(r3) : "r"(addr))
#define MMA_BF16(c, a0,a1,a2,a3, b0,b1) \
    asm volatile("mma.sync.aligned.m16n8k16.row.col.f32.bf16.bf16.f32 " \
        "{%0,%1,%2,%3},{%4,%5,%6,%7},{%8,%9},{%0,%1,%2,%3};" \
        : "+f"((c)[0]),"+f"((c)[1]),"+f"((c)[2]),"+f"((c)[3]) \
        : "r"(a0),"r"(a1),"r"(a2),"r"(a3),"r"(b0),"r"(b1))

// ---------------------------------------------------------------------------
// Persistent kernel: 80 CTAs (40 h-tiles x 2 batch halves) x 256 threads.
// 8 warps = 4m x 2n (warp tile m16 x n16); 4 acc chains; x in fragment regs.
// W prefetch for next step's first 4 slabs issued BEFORE the grid barrier.
// ---------------------------------------------------------------------------
__global__ void __launch_bounds__(256, 1) rnn_kernel(const float* __restrict__ b_rec,
                                                     float* __restrict__ out) {
    extern __shared__ char sm[];
    uint32_t sb;
    asm("{ .reg .u64 t; cvta.to.shared.u64 t, %1; cvt.u32.u64 %0, t; }" : "=r"(sb) : "l"(sm));
    const int tid = threadIdx.x, wid = tid >> 5, lane = tid & 31;
    const int wm = wid & 3, nh = wid >> 2;
    const int g = lane >> 2, cq = lane & 3;
    const int cta = blockIdx.x, tau = cta >> 1, bh = (cta & 1) << 5;
    const int a = tau/10, ti = tau - 10*a;
    const int hbase = (ti<8) ? a*512 + ti*64 : 2048 + a*128 + (ti-8)*64;
    const int nE    = (a==1||a==2)?12:8;
    const int nS    = nE + 1 + ((a==0)?1:0);
    const int kE0   = (a>0?a-1:0)*512;
    const int kI0   = 2048 + a*128;
    const int baseA = (a==0)?0:(a==1)?100:(a==2)?230:360;
    const int blkbase = baseA + ti*nS;

    const float bias0 = b_rec[hbase + wm*16 + g];
    const float bias1 = b_rec[hbase + wm*16 + 8 + g];

    // ldmatrix lane geometry (chunk-XOR swizzle within 256B rows, 16 chunks)
    const int lr = lane & 7, half = (lane >> 3) & 1, kbit = lane >> 4;
    const int rowA = wm*16 + half*8 + lr;
    const int rowB = nh*16 + half*8 + lr;
    const uint32_t aoff = (uint32_t)rowA << 8;
    const uint32_t boff = 16384u + ((uint32_t)rowB << 8);
    const int axor = rowA & 7, bxor = rowB & 7;

    float x0[4], x1[4];
    #pragma unroll
    for (int k = 0; k < 4; k++) { x0[k] = 0.f; x1[k] = 0.f; }

    float* OUT = (float*)(sm + OUT_OFF);   // [32b][68] padded fp32

    const __nv_bfloat16* rin  = g_r[0];
    __nv_bfloat16*       rout = g_r[1];

    // W issuer (one commit per call)
    auto issue_W = [&](int s) {
        uint32_t st = sb + (uint32_t)(s % NSTG) * STAGE_SZ;
        const __nv_bfloat16* wsrc = g_Wb + (size_t)(blkbase + s) * 8192;
        #pragma unroll
        for (int it = 0; it < 4; it++) {
            int c = tid + 256*it;              // 1024 W chunks of 16B
            int row = c >> 4, ch = c & 15;
            cp16(st + ((uint32_t)row << 8) + (uint32_t)((ch ^ (row & 7)) << 4),
                 wsrc + c*8);
        }
    };

    // pre-loop: W for step 0, slabs 0..3
    issue_W(0); cpcommit();
    issue_W(1); cpcommit();
    issue_W(2); cpcommit();
    issue_W(3); cpcommit();

    for (int t = 0; t < TSTEPS; t++) {
        const __nv_bfloat16* __restrict__ inp = g_in + (size_t)t * (BATCH*IN_DIM);

        auto issue_r = [&](int s) {
            uint32_t st = sb + (uint32_t)(s % NSTG) * STAGE_SZ + 16384u;
            #pragma unroll
            for (int it = 0; it < 2; it++) {
                int c = tid + 256*it;          // 512 r chunks
                int row = c >> 4, ch = c & 15;
                const __nv_bfloat16* src;
                if (s < nE)       src = rin + (size_t)(bh + row)*HID + kE0 + 128*s + ch*8;
                else if (s == nE) src = rin + (size_t)(bh + row)*HID + kI0 + ch*8;
                else              src = inp + (size_t)(bh + row)*IN_DIM + ch*8;
                cp16(st + ((uint32_t)row << 8) + (uint32_t)((ch ^ (row & 7)) << 4), src);
            }
        };

        // r for slabs 0..3 (groups 4..7 of this step)
        issue_r(0); cpcommit();
        issue_r(1); cpcommit();
        issue_r(2); cpcommit();
        issue_r(3); cpcommit();

        float acc0[2][4], acc1[2][4];
        #pragma unroll
        for (int p = 0; p < 2; p++)
            #pragma unroll
            for (int k = 0; k < 4; k++) { acc0[p][k] = 0.f; acc1[p][k] = 0.f; }

        for (int s = 0; s < nS; s++) {
            int ahead = nS - 1 - s; if (ahead > 3) ahead = 3;
            cpwait(ahead);
            __syncthreads();
            if (s + 4 < nS) { issue_W(s + 4); issue_r(s + 4); cpcommit(); }

            uint32_t st = sb + (uint32_t)(s % NSTG) * STAGE_SZ;
            uint32_t pa = st + aoff, pb = st + boff;
            #pragma unroll
            for (int c = 0; c < 8; c++) {
                uint32_t ra0, ra1, ra2, ra3, rb0, rb1, rb2, rb3;
                LDSM_X4(ra0, ra1, ra2, ra3, pa + (uint32_t)(((2*c + kbit) ^ axor) << 4));
                LDSM_X4(rb0, rb1, rb2, rb3, pb + (uint32_t)(((2*c + kbit) ^ bxor) << 4));
                MMA_BF16(acc0[c & 1], ra0, ra1, ra2, ra3, rb0, rb2);
                MMA_BF16(acc1[c & 1], ra0, ra1, ra2, ra3, rb1, rb3);
            }
        }

        // epilogue: x update + retanh, transpose via smem, coalesced writes
        {
            int hg = wm*16 + g;
            #pragma unroll
            for (int j = 0; j < 2; j++) {
                float* a0 = j ? acc1[0] : acc0[0];
                float* a1 = j ? acc1[1] : acc0[1];
                float* xx = j ? x1 : x0;
                int b0 = nh*16 + j*8 + 2*cq;
                float xv, r;
                xv = 0.8f*xx[0] + 0.2f*(a0[0] + a1[0] + bias0); xx[0] = xv;
                r = (xv > 0.f) ? tanhf(xv) : 0.f; OUT[(b0  )*68 + hg    ] = r;
                xv = 0.8f*xx[1] + 0.2f*(a0[1] + a1[1] + bias0); xx[1] = xv;
                r = (xv > 0.f) ? tanhf(xv) : 0.f; OUT[(b0+1)*68 + hg    ] = r;
                xv = 0.8f*xx[2] + 0.2f*(a0[2] + a1[2] + bias1); xx[2] = xv;
                r = (xv > 0.f) ? tanhf(xv) : 0.f; OUT[(b0  )*68 + hg + 8] = r;
                xv = 0.8f*xx[3] + 0.2f*(a0[3] + a1[3] + bias1); xx[3] = xv;
                r = (xv > 0.f) ? tanhf(xv) : 0.f; OUT[(b0+1)*68 + hg + 8] = r;
            }
        }
        __syncthreads();
        #pragma unroll
        for (int it = 0; it < 2; it++) {
            int f = tid + 256*it;                 // 512 float4s: 32b x 16 h-quads
            int b = f >> 4, hq = f & 15;
            float4 v = *(const float4*)&OUT[b*68 + hq*4];
            *(float4*)&out[(size_t)t*(BATCH*HID) + (size_t)(bh + b)*HID + hbase + hq*4] = v;
            uint32_t p0, p1;
            asm("cvt.rn.bf16x2.f32 %0, %1, %2;" : "=r"(p0) : "f"(v.y), "f"(v.x));
            asm("cvt.rn.bf16x2.f32 %0, %1, %2;" : "=r"(p1) : "f"(v.w), "f"(v.z));
            uint2 pk; pk.x = p0; pk.y = p1;
            *(uint2*)(rout + (size_t)(bh + b)*HID + hbase + hq*4) = pk;
        }

        // swap ping-pong, pre-issue next step's W while waiting on the barrier
        { const __nv_bfloat16* tmp = rin; rin = rout; rout = (__nv_bfloat16*)tmp; }
        if (t + 1 < TSTEPS) {
            issue_W(0); cpcommit();
            issue_W(1); cpcommit();
            issue_W(2); cpcommit();
            issue_W(3); cpcommit();
        }

        // grid barrier (monotonic counter; 80 CTAs co-resident)
        __threadfence();
        __syncthreads();
        if (tid == 0) {
            atomicAdd(&g_bar, 1);
            while (*((volatile int*)&g_bar) < GRID*(t+1)) { }
        }
        __syncthreads();
    }
}

// ---------------------------------------------------------------------------
extern "C" void kernel_launch(void* const* d_in, const int* in_sizes, int n_in,
                              void* d_out, int out_size) {
    const float *inputs = nullptr, *W_rec = nullptr,
                *b_rec = nullptr,  *W_in  = nullptr;
    for (int i = 0; i < n_in; i++) {
        long n = (long)in_sizes[i];
        if      (n == (long)TSTEPS*BATCH*IN_DIM) inputs = (const float*)d_in[i];
        else if (n == (long)HID*HID)             W_rec  = (const float*)d_in[i];
        else if (n == (long)HID)                 b_rec  = (const float*)d_in[i];
        else if (n == (long)HID*IN_DIM)          W_in   = (const float*)d_in[i];
    }
    float* out = (float*)d_out;

    cudaFuncSetAttribute(rnn_kernel, cudaFuncAttributeMaxDynamicSharedMemorySize, SMEM_TOTAL);

    build_W <<<(450*8192 + 255)/256, 256>>>(W_rec, W_in);
    build_in<<<(TSTEPS*BATCH*IN_DIM + 255)/256, 256>>>(inputs);
    init_k  <<<(BATCH*HID + 255)/256, 256>>>();
    rnn_kernel<<<GRID, 256, SMEM_TOTAL>>>(b_rec, out);
}

// round 11
// speedup vs baseline: 3.1387x; 1.2734x over previous
#include <cuda_runtime.h>
#include <cuda_bf16.h>
#include <math.h>
#include <stdint.h>

#define HID    2560
#define BATCH  64
#define TSTEPS 500
#define IN_DIM 128
#define GRID   80
#define NSTG   5
#define STAGE_SZ 24576                 // 16KB W (64x256B) + 8KB r (32x256B)
#define WBYTES 16384
#define RBYTES 8192
#define OUT_OFF (NSTG*STAGE_SZ)        // 122880
#define MB_OFF  (OUT_OFF + 8704)       // 131584
#define SMEM_TOTAL (MB_OFF + 128)      // 131712

// static scratch (allocations forbidden)
__device__ __nv_bfloat16 g_Wb[450*8192];            // pre-swizzled W_eff slabs [slab][64h][128k]
__device__ __nv_bfloat16 g_in[TSTEPS*64*IN_DIM];    // pre-swizzled inputs [t][64b][128k]
__device__ __nv_bfloat16 g_rs[2][20*64*128];        // swizzled rates [slab128][64b][128k]
__device__ int g_bar;

// ---------------------------------------------------------------------------
// Builders. Connectivity (validated at rel_err 1e-8 in fp32 rounds):
//  E col k(<2048): |area(h)-area(k)|<=1, +|w|; I col: same area, -|w|;
//  diagonal removed; input cols only for area-0 rows, +|w_in|.
// 128k slabs per 64h tile: nE {8,12,12,8}, +1 I, (+1 input if area 0)
// → nS {10,13,13,9}; slab bases per area {0,100,230,360}; total 450.
// Swizzle baked into global: 16B chunk ch of row r stored at ch ^ (r&7).
// ---------------------------------------------------------------------------
__global__ void build_W(const float* __restrict__ W_rec, const float* __restrict__ W_in) {
    int idx = blockIdx.x*blockDim.x + threadIdx.x;
    if (idx >= 450*8192) return;
    int blk = idx >> 13, e = idx & 8191;
    int hl = e >> 7, cc = e & 127;
    int a    = (blk<100)?0:(blk<230)?1:(blk<360)?2:3;
    int base = (a==0)?0:(a==1)?100:(a==2)?230:360;
    int nE   = (a==1||a==2)?12:8;
    int nS   = nE + 1 + ((a==0)?1:0);
    int ti = (blk - base)/nS;
    int i  = (blk - base) - ti*nS;
    int hbase = (ti<8) ? a*512 + ti*64 : 2048 + a*128 + (ti-8)*64;
    int h = hbase + hl;
    float v = 0.f;
    if (i < nE) {
        int k = (a>0?a-1:0)*512 + i*128 + cc;
        if (k != h) v = fabsf(W_rec[(size_t)h*HID + k]);
    } else if (i == nE) {
        int k = 2048 + a*128 + cc;
        if (k != h) v = -fabsf(W_rec[(size_t)h*HID + k]);
    } else {
        v = fabsf(W_in[(size_t)h*IN_DIM + cc]);
    }
    int dst = blk*8192 + hl*128 + ((((cc>>3) ^ (hl&7)))<<3) + (cc&7);
    g_Wb[dst] = __float2bfloat16_rn(v);
}

__global__ void build_in(const float* __restrict__ in) {
    int idx = blockIdx.x*blockDim.x + threadIdx.x;
    if (idx >= TSTEPS*64*IN_DIM) return;
    int t = idx >> 13, rem = idx & 8191;
    int b = rem >> 7, k = rem & 127;
    int dst = t*8192 + b*128 + ((((k>>3) ^ (b&7)))<<3) + (k&7);
    g_in[dst] = __float2bfloat16_rn(in[idx]);
}

__global__ void init_k() {
    int idx = blockIdx.x*blockDim.x + threadIdx.x;
    if (idx < 20*64*128) g_rs[0][idx] = __float2bfloat16_rn(0.f);
    if (idx == 0) g_bar = 0;
}

// ---------------------------------------------------------------------------
#define MBAR_INIT(m, c) \
    asm volatile("mbarrier.init.shared.b64 [%0], %1;" :: "r"(m), "r"(c) : "memory")
#define MBAR_EXPECT_TX(m, b) \
    asm volatile("mbarrier.arrive.expect_tx.shared.b64 _, [%0], %1;" :: "r"(m), "r"(b) : "memory")
#define MBAR_ARRIVE(m) \
    asm volatile("mbarrier.arrive.shared.b64 _, [%0];" :: "r"(m) : "memory")
#define BULK_G2S(dst, src, bytes, mbar) \
    asm volatile("cp.async.bulk.shared::cta.global.mbarrier::complete_tx::bytes [%0], [%1], %2, [%3];" \
                 :: "r"(dst), "l"(src), "r"(bytes), "r"(mbar) : "memory")
__device__ __forceinline__ void mbar_wait(uint32_t mbar, uint32_t parity) {
    uint32_t done;
    asm volatile("{\n\t.reg .pred p;\n\t"
                 "mbarrier.try_wait.parity.acquire.cta.shared::cta.b64 p, [%1], %2;\n\t"
                 "selp.b32 %0, 1, 0, p;\n\t}"
                 : "=r"(done) : "r"(mbar), "r"(parity) : "memory");
    while (!done) {
        asm volatile("{\n\t.reg .pred p;\n\t"
                     "mbarrier.try_wait.parity.acquire.cta.shared::cta.b64 p, [%1], %2, 0x989680;\n\t"
                     "selp.b32 %0, 1, 0, p;\n\t}"
                     : "=r"(done) : "r"(mbar), "r"(parity) : "memory");
    }
}
#define LDSM_X4(r0,r1,r2,r3,addr) \
    asm volatile("ldmatrix.sync.aligned.m8n8.x4.shared.b16 {%0,%1,%2,%3}, [%4];" \
        : "=r"(r0),"=r"(r1),"=r"(r2),"=r"(r3) : "r"(addr))
#define MMA_BF16(c, a0,a1,a2,a3, b0,b1) \
    asm volatile("mma.sync.aligned.m16n8k16.row.col.f32.bf16.bf16.f32 " \
        "{%0,%1,%2,%3},{%4,%5,%6,%7},{%8,%9},{%0,%1,%2,%3};" \
        : "+f"((c)[0]),"+f"((c)[1]),"+f"((c)[2]),"+f"((c)[3]) \
        : "r"(a0),"r"(a1),"r"(a2),"r"(a3),"r"(b0),"r"(b1))

// ---------------------------------------------------------------------------
// Persistent kernel: 80 CTAs x 288 threads.
// Warp 8 = bulk-copy producer (5-stage mbarrier ring); warps 0-7 = LDSM+MMA.
// ---------------------------------------------------------------------------
__global__ void __launch_bounds__(288, 1) rnn_kernel(const float* __restrict__ b_rec,
                                                     float* __restrict__ out) {
    extern __shared__ char sm[];
    uint32_t sb;
    asm("{ .reg .u64 t; cvta.to.shared.u64 t, %1; cvt.u32.u64 %0, t; }" : "=r"(sb) : "l"(sm));
    const uint32_t MB = sb + MB_OFF;   // full[5]@+0, empty[5]@+40
    const int tid = threadIdx.x, wid = tid >> 5, lane = tid & 31;
    const int wm = wid & 3, nh = (wid >> 2) & 1;
    const int g = lane >> 2, cq = lane & 3;
    const int cta = blockIdx.x, tau = cta >> 1, bh = (cta & 1) << 5;
    const int a = tau/10, ti = tau - 10*a;
    const int hbase = (ti<8) ? a*512 + ti*64 : 2048 + a*128 + (ti-8)*64;
    const int nE    = (a==1||a==2)?12:8;
    const int nS    = nE + 1 + ((a==0)?1:0);
    const int kslab0 = (a>0?(a-1)*4:0);     // first E r-slab
    const int islab  = 16 + a;              // I r-slab
    const int baseA = (a==0)?0:(a==1)?100:(a==2)?230:360;
    const int blkbase = baseA + ti*nS;

    const float bias0 = b_rec[hbase + wm*16 + g];
    const float bias1 = b_rec[hbase + wm*16 + 8 + g];

    // ldmatrix lane geometry (chunk-XOR swizzle within 256B rows)
    const int lr = lane & 7, half = (lane >> 3) & 1, kbit = lane >> 4;
    const int rowA = wm*16 + half*8 + lr;
    const int rowB = nh*16 + half*8 + lr;
    const uint32_t aoff = (uint32_t)rowA << 8;
    const uint32_t boff = 16384u + ((uint32_t)rowB << 8);
    const int axor = rowA & 7, bxor = rowB & 7;

    if (tid == 0) {
        #pragma unroll
        for (int s = 0; s < NSTG; s++) {
            MBAR_INIT(MB + s*8, 1);        // full: expect_tx arrival + tx bytes
            MBAR_INIT(MB + 40 + s*8, 8);   // empty: 8 consumer-warp arrivals
        }
    }
    __syncthreads();

    float x0[4], x1[4];
    #pragma unroll
    for (int k = 0; k < 4; k++) { x0[k] = 0.f; x1[k] = 0.f; }

    float* OUT = (float*)(sm + OUT_OFF);   // [32b][68] padded fp32

    const __nv_bfloat16* rin  = g_rs[0];
    __nv_bfloat16*       rout = g_rs[1];

    const bool prod = (tid == 256);        // single producer thread (warp 8, lane 0)
    int pf = 0;                            // producer fill counter
    int cstg = 0, cph = 0;                 // consumer ring cursor

    // preamble: W bulks for step 0, slabs 0..3
    if (prod) {
        #pragma unroll
        for (int j = 0; j < 4; j++) {
            int stg = pf % NSTG;
            MBAR_EXPECT_TX(MB + stg*8, STAGE_SZ);
            BULK_G2S(sb + stg*STAGE_SZ,
                     g_Wb + (size_t)(blkbase + j)*8192, WBYTES, MB + stg*8);
            pf++;
        }
    }

    for (int t = 0; t < TSTEPS; t++) {
        const __nv_bfloat16* __restrict__ inp = g_in + (size_t)t * 8192;

        if (prod) {
            // r bulks for the 4 prefetched fills (slabs 0..3, all E-type)
            #pragma unroll
            for (int j = 0; j < 4; j++) {
                int stg = (pf - 4 + j + NSTG) % NSTG;
                BULK_G2S(sb + stg*STAGE_SZ + WBYTES,
                         rin + (size_t)(kslab0 + j)*8192 + bh*128, RBYTES, MB + stg*8);
            }
            // remaining slabs: full W+r
            for (int s = 4; s < nS; s++) {
                int stg = pf % NSTG;
                if (pf >= NSTG) mbar_wait(MB + 40 + stg*8, (uint32_t)((pf/NSTG + 1) & 1));
                MBAR_EXPECT_TX(MB + stg*8, STAGE_SZ);
                BULK_G2S(sb + stg*STAGE_SZ,
                         g_Wb + (size_t)(blkbase + s)*8192, WBYTES, MB + stg*8);
                const __nv_bfloat16* rsrc;
                if (s < nE)       rsrc = rin + (size_t)(kslab0 + s)*8192 + bh*128;
                else if (s == nE) rsrc = rin + (size_t)islab*8192 + bh*128;
                else              rsrc = inp + bh*128;
                BULK_G2S(sb + stg*STAGE_SZ + WBYTES, rsrc, RBYTES, MB + stg*8);
                pf++;
            }
        }

        float acc0[2][4], acc1[2][4];
        #pragma unroll
        for (int p = 0; p < 2; p++)
            #pragma unroll
            for (int k = 0; k < 4; k++) { acc0[p][k] = 0.f; acc1[p][k] = 0.f; }

        if (wid < 8) {
            for (int s = 0; s < nS; s++) {
                mbar_wait(MB + cstg*8, (uint32_t)cph);
                uint32_t st = sb + (uint32_t)cstg * STAGE_SZ;
                uint32_t pa = st + aoff, pb = st + boff;
                #pragma unroll
                for (int c = 0; c < 8; c++) {
                    uint32_t ra0, ra1, ra2, ra3, rb0, rb1, rb2, rb3;
                    LDSM_X4(ra0, ra1, ra2, ra3, pa + (uint32_t)(((2*c + kbit) ^ axor) << 4));
                    LDSM_X4(rb0, rb1, rb2, rb3, pb + (uint32_t)(((2*c + kbit) ^ bxor) << 4));
                    MMA_BF16(acc0[c & 1], ra0, ra1, ra2, ra3, rb0, rb2);
                    MMA_BF16(acc1[c & 1], ra0, ra1, ra2, ra3, rb1, rb3);
                }
                if (lane == 0) MBAR_ARRIVE(MB + 40 + cstg*8);
                if (++cstg == NSTG) { cstg = 0; cph ^= 1; }
            }

            // epilogue: x update + retanh into OUT
            int hg = wm*16 + g;
            #pragma unroll
            for (int j = 0; j < 2; j++) {
                float* a0 = j ? acc1[0] : acc0[0];
                float* a1 = j ? acc1[1] : acc0[1];
                float* xx = j ? x1 : x0;
                int b0 = nh*16 + j*8 + 2*cq;
                float xv, r;
                xv = 0.8f*xx[0] + 0.2f*(a0[0] + a1[0] + bias0); xx[0] = xv;
                r = (xv > 0.f) ? tanhf(xv) : 0.f; OUT[(b0  )*68 + hg    ] = r;
                xv = 0.8f*xx[1] + 0.2f*(a0[1] + a1[1] + bias0); xx[1] = xv;
                r = (xv > 0.f) ? tanhf(xv) : 0.f; OUT[(b0+1)*68 + hg    ] = r;
                xv = 0.8f*xx[2] + 0.2f*(a0[2] + a1[2] + bias1); xx[2] = xv;
                r = (xv > 0.f) ? tanhf(xv) : 0.f; OUT[(b0  )*68 + hg + 8] = r;
                xv = 0.8f*xx[3] + 0.2f*(a0[3] + a1[3] + bias1); xx[3] = xv;
                r = (xv > 0.f) ? tanhf(xv) : 0.f; OUT[(b0+1)*68 + hg + 8] = r;
            }
        } else {
            cstg = (cstg + nS) % NSTG;     // keep cursor consistent (unused by prod)
        }
        __syncthreads();
        if (tid < 256) {
            #pragma unroll
            for (int it = 0; it < 2; it++) {
                int f = tid + 256*it;             // 512 float4s: 32b x 16 h-quads
                int b = f >> 4, hq = f & 15;
                float4 v = *(const float4*)&OUT[b*68 + hq*4];
                *(float4*)&out[(size_t)t*(BATCH*HID) + (size_t)(bh + b)*HID + hbase + hq*4] = v;
                uint32_t p0, p1;
                asm("cvt.rn.bf16x2.f32 %0, %1, %2;" : "=r"(p0) : "f"(v.y), "f"(v.x));
                asm("cvt.rn.bf16x2.f32 %0, %1, %2;" : "=r"(p1) : "f"(v.w), "f"(v.z));
                uint2 pk; pk.x = p0; pk.y = p1;
                int k   = (hbase & 127) + hq*4;
                int ch  = k >> 3;
                int gb  = bh + b;
                int dst = (hbase >> 7)*8192 + gb*128 + ((ch ^ (gb & 7)) << 3) + (k & 7);
                *(uint2*)(rout + dst) = pk;
            }
        }

        // swap ping-pong; prefetch next step's W into freed stages (pre-barrier)
        { const __nv_bfloat16* tmp = rin; rin = rout; rout = (__nv_bfloat16*)tmp; }
        if (t + 1 < TSTEPS && prod) {
            #pragma unroll
            for (int j = 0; j < 4; j++) {
                int stg = pf % NSTG;
                mbar_wait(MB + 40 + stg*8, (uint32_t)((pf/NSTG + 1) & 1));
                MBAR_EXPECT_TX(MB + stg*8, STAGE_SZ);
                BULK_G2S(sb + stg*STAGE_SZ,
                         g_Wb + (size_t)(blkbase + j)*8192, WBYTES, MB + stg*8);
                pf++;
            }
        }

        // grid barrier (monotonic counter; 80 CTAs co-resident)
        __threadfence();
        __syncthreads();
        if (tid == 0) {
            atomicAdd(&g_bar, 1);
            while (*((volatile int*)&g_bar) < GRID*(t+1)) { }
        }
        __syncthreads();
    }
}

// ---------------------------------------------------------------------------
extern "C" void kernel_launch(void* const* d_in, const int* in_sizes, int n_in,
                              void* d_out, int out_size) {
    const float *inputs = nullptr, *W_rec = nullptr,
                *b_rec = nullptr,  *W_in  = nullptr;
    for (int i = 0; i < n_in; i++) {
        long n = (long)in_sizes[i];
        if      (n == (long)TSTEPS*BATCH*IN_DIM) inputs = (const float*)d_in[i];
        else if (n == (long)HID*HID)             W_rec  = (const float*)d_in[i];
        else if (n == (long)HID)                 b_rec  = (const float*)d_in[i];
        else if (n == (long)HID*IN_DIM)          W_in   = (const float*)d_in[i];
    }
    float* out = (float*)d_out;

    cudaFuncSetAttribute(rnn_kernel, cudaFuncAttributeMaxDynamicSharedMemorySize, SMEM_TOTAL);

    build_W <<<(450*8192 + 255)/256, 256>>>(W_rec, W_in);
    build_in<<<(TSTEPS*64*IN_DIM + 255)/256, 256>>>(inputs);
    init_k  <<<(20*64*128 + 255)/256, 256>>>();
    rnn_kernel<<<GRID, 288, SMEM_TOTAL>>>(b_rec, out);
}